// round 3
// baseline (speedup 1.0000x reference)
#include <cuda_runtime.h>
#include <math.h>

#define NN   100000      // nodes
#define NI   2000000     // incidences
#define NH   300000      // hyperedges
#define IND  92          // input feature dim
#define HD   64          // hidden dim
#define AD   35          // hedge attr dim
#define ADP  36          // padded attr stride (16B-aligned rows)
#define HOUT 128
#define NG   512
#define NL   3
#define MD   163         // 2*HD + AD

#define NT   16          // nodes per GEMM tile
#define NTILES (NN / NT) // 6250 exactly

// ---------------- scratch (device globals; no allocation allowed) ------------
__device__ __align__(16) float g_h[NN * HD];       // node features (in-place updated)
__device__ __align__(16) float g_hsum[NH * HD];    // hedge accumulation
__device__ __align__(16) float g_nsum[NN * HD];    // node accumulation
__device__ __align__(16) float g_na[NN * ADP];     // node attr-mean accumulation (padded)
__device__ __align__(16) float g_pool[NG * HD];
__device__ __align__(16) float g_ncnt[NN];
__device__ __align__(16) float g_hcnt[NH];
__device__ __align__(16) float g_ninv[NN];
__device__ __align__(16) float g_nhas[NN];
__device__ __align__(16) float g_hinv[NH];
__device__ __align__(16) float g_pcnt[NG];

// ---------------- helpers ----------------------------------------------------
__device__ __forceinline__ void red_add_f4(float* a, float4 v) {
    asm volatile("red.global.add.v4.f32 [%0], {%1, %2, %3, %4};"
                 :: "l"(a), "f"(v.x), "f"(v.y), "f"(v.z), "f"(v.w) : "memory");
}
__device__ __forceinline__ void red_add_f1(float* a, float v) {
    asm volatile("red.global.add.f32 [%0], %1;" :: "l"(a), "f"(v) : "memory");
}
__device__ __forceinline__ float sigmoidf_(float x) {
    return 1.0f / (1.0f + __expf(-x));
}
__device__ __forceinline__ float softplusf_(float x) {
    if (x > 20.0f) return x;
    return log1pf(expf(x));
}

// ---------------- prelude zero: na, counts, pool ------------------------------
__global__ void zero_prelude_kernel() {
    int stride = gridDim.x * blockDim.x;
    int t0 = blockIdx.x * blockDim.x + threadIdx.x;
    float4 z = make_float4(0.f, 0.f, 0.f, 0.f);
    float4* na   = reinterpret_cast<float4*>(g_na);
    float4* ncnt = reinterpret_cast<float4*>(g_ncnt);
    float4* hcnt = reinterpret_cast<float4*>(g_hcnt);
    float4* pl   = reinterpret_cast<float4*>(g_pool);
    float4* pc   = reinterpret_cast<float4*>(g_pcnt);
    for (int i = t0; i < NN*ADP/4; i += stride) na[i] = z;
    for (int i = t0; i < NN/4;     i += stride) ncnt[i] = z;
    for (int i = t0; i < NH/4;     i += stride) hcnt[i] = z;
    for (int i = t0; i < NG*HD/4;  i += stride) pl[i] = z;
    for (int i = t0; i < NG/4;     i += stride) pc[i] = z;
}

// ---------------- inverses ----------------------------------------------------
__global__ void inv_kernel() {
    int i = blockIdx.x * blockDim.x + threadIdx.x;
    if (i < NH) {
        float c = g_hcnt[i];
        g_hinv[i] = 1.0f / fmaxf(c, 1.0f);
    }
    if (i < NN) {
        float c = g_ncnt[i];
        g_ninv[i] = 1.0f / fmaxf(c, 1.0f);
        g_nhas[i] = (c > 0.0f) ? 1.0f : 0.0f;
    }
}

// ---------------- attr scatter + fused counts ---------------------------------
// 8 lanes per incidence: lanes 0..7 each handle one float4 chunk (floats 0..31);
// lane 7 also handles the scalar tail 32..34; lanes 0/1 do the count reds.
__global__ void attr_scatter_kernel(const int* __restrict__ inod,
                                    const int* __restrict__ ihed,
                                    const float* __restrict__ attr) {
    int t = blockIdx.x * blockDim.x + threadIdx.x;
    if (t >= NI * 8) return;
    int i = t >> 3, c = t & 7;
    int nd = inod[i], he = ihed[i];
    const float* ap = attr + (size_t)he * AD + c * 4;
    float4 v = make_float4(__ldg(ap), __ldg(ap + 1), __ldg(ap + 2), __ldg(ap + 3));
    red_add_f4(g_na + nd * ADP + c * 4, v);
    if (c == 0) red_add_f1(g_ncnt + nd, 1.0f);
    if (c == 1) red_add_f1(g_hcnt + he, 1.0f);
    if (c == 7) {
        const float* tp = attr + (size_t)he * AD + 32;
        float* dp = g_na + nd * ADP + 32;
        red_add_f1(dp + 0, __ldg(tp + 0));
        red_add_f1(dp + 1, __ldg(tp + 1));
        red_add_f1(dp + 2, __ldg(tp + 2));
    }
}

// ---------------- embed GEMM: h = x @ W_embed + b (+ zero hsum/nsum) ----------
__global__ void embed_kernel(const float* __restrict__ x,
                             const float* __restrict__ W,
                             const float* __restrict__ b) {
    __shared__ float Ws[IND * HD];
    __shared__ float bs[HD];
    __shared__ float xs[NT][IND];
    int tid = threadIdx.x;
    int stride = gridDim.x * blockDim.x;
    int t0 = blockIdx.x * blockDim.x + tid;

    // zero the layer-0 accumulators (this kernel doesn't touch them otherwise)
    {
        float4 z = make_float4(0.f, 0.f, 0.f, 0.f);
        float4* hs = reinterpret_cast<float4*>(g_hsum);
        float4* ns = reinterpret_cast<float4*>(g_nsum);
        for (int i = t0; i < NH*HD/4; i += stride) hs[i] = z;
        for (int i = t0; i < NN*HD/4; i += stride) ns[i] = z;
    }

    for (int idx = tid; idx < IND * HD; idx += 256) Ws[idx] = W[idx];
    if (tid < HD) bs[tid] = b[tid];
    __syncthreads();

    int j = tid & 63, g = tid >> 6;  // g in 0..3, each handles 4 nodes
    for (int tile = blockIdx.x; tile < NTILES; tile += gridDim.x) {
        int base = tile * NT;
        for (int idx = tid; idx < NT * IND; idx += 256) {
            int n = idx / IND, k = idx % IND;
            xs[n][k] = x[(size_t)(base + n) * IND + k];
        }
        __syncthreads();
        float a0 = 0.f, a1 = 0.f, a2 = 0.f, a3 = 0.f;
        int n0 = g * 4;
        #pragma unroll 4
        for (int k = 0; k < IND; k++) {
            float w = Ws[k * HD + j];
            a0 += w * xs[n0 + 0][k];
            a1 += w * xs[n0 + 1][k];
            a2 += w * xs[n0 + 2][k];
            a3 += w * xs[n0 + 3][k];
        }
        float bb = bs[j];
        g_h[(base + n0 + 0) * HD + j] = a0 + bb;
        g_h[(base + n0 + 1) * HD + j] = a1 + bb;
        g_h[(base + n0 + 2) * HD + j] = a2 + bb;
        g_h[(base + n0 + 3) * HD + j] = a3 + bb;
        __syncthreads();
    }
}

// ---------------- scatter node -> hedge (sum of h rows) ----------------------
// 16 lanes per incidence, one float4 each.
__global__ void scatter_n2h_kernel(const int* __restrict__ inod,
                                   const int* __restrict__ ihed) {
    int t = blockIdx.x * blockDim.x + threadIdx.x;
    if (t >= NI * 16) return;
    int i = t >> 4, c = t & 15;
    int nd = inod[i], he = ihed[i];
    float4 v = __ldg(reinterpret_cast<const float4*>(g_h + nd * HD + c * 4));
    red_add_f4(g_hsum + he * HD + c * 4, v);
}

// ---------------- scatter hedge -> node (sum of hedge means) -----------------
__global__ void scatter_h2n_kernel(const int* __restrict__ inod,
                                   const int* __restrict__ ihed) {
    int t = blockIdx.x * blockDim.x + threadIdx.x;
    if (t >= NI * 16) return;
    int i = t >> 4, c = t & 15;
    int nd = inod[i], he = ihed[i];
    float inv = __ldg(g_hinv + he);
    float4 v = __ldg(reinterpret_cast<const float4*>(g_hsum + he * HD + c * 4));
    v.x *= inv; v.y *= inv; v.z *= inv; v.w *= inv;
    red_add_f4(g_nsum + nd * HD + c * 4, v);
}

// ---------------- per-node update: z@[Wf|Wc] + gated softplus ----------------
// Also re-zeroes its own nsum tiles + grid-strides hsum zero for the next layer.
// Dynamic smem: Wcat[163*128] + z[NT*164] + bf[64] + bc[64]
__global__ void node_update_kernel(const float* __restrict__ Wf,
                                   const float* __restrict__ bf,
                                   const float* __restrict__ Wc,
                                   const float* __restrict__ bc,
                                   int layer) {
    extern __shared__ float sm[];
    float* Wsm = sm;                    // MD*128
    float* zs  = sm + MD * 128;         // NT*164
    float* bfs = zs + NT * 164;         // 64
    float* bcs = bfs + 64;              // 64

    const float* Wfl = Wf + (size_t)layer * MD * HD;
    const float* Wcl = Wc + (size_t)layer * MD * HD;
    int tid = threadIdx.x;
    bool not_last = (layer < NL - 1);
    for (int idx = tid; idx < MD * 128; idx += 256) {
        int k = idx >> 7, c = idx & 127;
        Wsm[idx] = (c < HD) ? Wfl[k * HD + c] : Wcl[k * HD + (c - HD)];
    }
    if (tid < HD) { bfs[tid] = bf[layer * HD + tid]; bcs[tid] = bc[layer * HD + tid]; }
    __syncthreads();

    int j = tid & 63, g = tid >> 6;     // g in 0..3, each handles 4 nodes
    for (int tile = blockIdx.x; tile < NTILES; tile += gridDim.x) {
        int base = tile * NT;
        // build z rows: [h*has | nsum*ninv | na*ninv]
        for (int idx = tid; idx < NT * MD; idx += 256) {
            int n = idx / MD, k = idx % MD;
            int node = base + n;
            float v;
            if (k < HD)        v = g_h[node * HD + k] * g_nhas[node];
            else if (k < 2*HD) v = g_nsum[node * HD + (k - HD)] * g_ninv[node];
            else               v = g_na[node * ADP + (k - 2*HD)] * g_ninv[node];
            zs[n * 164 + k] = v;
        }
        __syncthreads();

        // nsum for this tile fully consumed -> zero it for the next layer
        // (tile is private to this block; NT*HD/4 == 256 float4s == one per thread)
        if (not_last)
            reinterpret_cast<float4*>(g_nsum + base * HD)[tid] =
                make_float4(0.f, 0.f, 0.f, 0.f);

        float f0=0.f,f1=0.f,f2=0.f,f3=0.f, c0=0.f,c1=0.f,c2=0.f,c3=0.f;
        int n0 = g * 4;
        const float4* z0p = reinterpret_cast<const float4*>(zs + (n0 + 0) * 164);
        const float4* z1p = reinterpret_cast<const float4*>(zs + (n0 + 1) * 164);
        const float4* z2p = reinterpret_cast<const float4*>(zs + (n0 + 2) * 164);
        const float4* z3p = reinterpret_cast<const float4*>(zs + (n0 + 3) * 164);
        #pragma unroll 4
        for (int kq = 0; kq < MD / 4; kq++) {       // k = 0..159 in float4 chunks
            float4 z0 = z0p[kq], z1 = z1p[kq], z2 = z2p[kq], z3 = z3p[kq];
            const float* wp = Wsm + (kq * 4) * 128 + j;
            {
                float wf = wp[0], wc = wp[64];
                f0 += wf * z0.x; c0 += wc * z0.x;
                f1 += wf * z1.x; c1 += wc * z1.x;
                f2 += wf * z2.x; c2 += wc * z2.x;
                f3 += wf * z3.x; c3 += wc * z3.x;
            }
            {
                float wf = wp[128], wc = wp[192];
                f0 += wf * z0.y; c0 += wc * z0.y;
                f1 += wf * z1.y; c1 += wc * z1.y;
                f2 += wf * z2.y; c2 += wc * z2.y;
                f3 += wf * z3.y; c3 += wc * z3.y;
            }
            {
                float wf = wp[256], wc = wp[320];
                f0 += wf * z0.z; c0 += wc * z0.z;
                f1 += wf * z1.z; c1 += wc * z1.z;
                f2 += wf * z2.z; c2 += wc * z2.z;
                f3 += wf * z3.z; c3 += wc * z3.z;
            }
            {
                float wf = wp[384], wc = wp[448];
                f0 += wf * z0.w; c0 += wc * z0.w;
                f1 += wf * z1.w; c1 += wc * z1.w;
                f2 += wf * z2.w; c2 += wc * z2.w;
                f3 += wf * z3.w; c3 += wc * z3.w;
            }
        }
        // tail k = 160..162
        #pragma unroll
        for (int k = (MD / 4) * 4; k < MD; k++) {
            float wf = Wsm[k * 128 + j];
            float wc = Wsm[k * 128 + j + 64];
            float z0 = zs[(n0 + 0) * 164 + k], z1 = zs[(n0 + 1) * 164 + k];
            float z2 = zs[(n0 + 2) * 164 + k], z3 = zs[(n0 + 3) * 164 + k];
            f0 += wf * z0; c0 += wc * z0;
            f1 += wf * z1; c1 += wc * z1;
            f2 += wf * z2; c2 += wc * z2;
            f3 += wf * z3; c3 += wc * z3;
        }
        float bfv = bfs[j], bcv = bcs[j];
        {
            int node = base + n0 + 0; float h = g_h[node * HD + j];
            g_h[node * HD + j] = softplusf_(sigmoidf_(f0 + bfv) * softplusf_(c0 + bcv) + h);
        }
        {
            int node = base + n0 + 1; float h = g_h[node * HD + j];
            g_h[node * HD + j] = softplusf_(sigmoidf_(f1 + bfv) * softplusf_(c1 + bcv) + h);
        }
        {
            int node = base + n0 + 2; float h = g_h[node * HD + j];
            g_h[node * HD + j] = softplusf_(sigmoidf_(f2 + bfv) * softplusf_(c2 + bcv) + h);
        }
        {
            int node = base + n0 + 3; float h = g_h[node * HD + j];
            g_h[node * HD + j] = softplusf_(sigmoidf_(f3 + bfv) * softplusf_(c3 + bcv) + h);
        }
        __syncthreads();
    }

    // hsum untouched by this kernel -> safe to zero here for the next layer
    if (not_last) {
        int stride = gridDim.x * blockDim.x;
        int t0 = blockIdx.x * blockDim.x + tid;
        float4 z = make_float4(0.f, 0.f, 0.f, 0.f);
        float4* hs = reinterpret_cast<float4*>(g_hsum);
        for (int i = t0; i < NH*HD/4; i += stride) hs[i] = z;
    }
}

// ---------------- pooling scatter --------------------------------------------
__global__ void pool_kernel(const int* __restrict__ batch) {
    int t = blockIdx.x * blockDim.x + threadIdx.x;
    if (t >= NN * 16) return;
    int i = t >> 4, c = t & 15;
    int gidx = batch[i];
    float4 v = __ldg(reinterpret_cast<const float4*>(g_h + i * HD + c * 4));
    red_add_f4(g_pool + gidx * HD + c * 4, v);
    if (c == 0) red_add_f1(g_pcnt + gidx, 1.0f);
}

// ---------------- head: softplus(pool@Wp + bp) @ Wo + bo ---------------------
__global__ void head_kernel(const float* __restrict__ Wp, const float* __restrict__ bp,
                            const float* __restrict__ Wo, const float* __restrict__ bo,
                            float* __restrict__ out) {
    __shared__ float ps[HD];
    __shared__ float rbuf[4];
    int g = blockIdx.x, tid = threadIdx.x;
    if (tid < HD)
        ps[tid] = g_pool[g * HD + tid] * (1.0f / fmaxf(g_pcnt[g], 1.0f));
    __syncthreads();
    float acc = bp[tid];
    #pragma unroll
    for (int k = 0; k < HD; k++) acc += ps[k] * Wp[k * HOUT + tid];
    float val = softplusf_(acc) * Wo[tid];
    #pragma unroll
    for (int o = 16; o; o >>= 1) val += __shfl_down_sync(0xffffffffu, val, o);
    if ((tid & 31) == 0) rbuf[tid >> 5] = val;
    __syncthreads();
    if (tid == 0) out[g] = rbuf[0] + rbuf[1] + rbuf[2] + rbuf[3] + bo[0];
}

// ---------------- launch ------------------------------------------------------
extern "C" void kernel_launch(void* const* d_in, const int* in_sizes, int n_in,
                              void* d_out, int out_size) {
    const float* x        = (const float*)d_in[0];
    const int*   inod     = (const int*)  d_in[1];
    const int*   ihed     = (const int*)  d_in[2];
    const float* attr     = (const float*)d_in[3];
    const int*   batch    = (const int*)  d_in[4];
    const float* W_embed  = (const float*)d_in[5];
    const float* b_embed  = (const float*)d_in[6];
    const float* Wf       = (const float*)d_in[7];
    const float* bf       = (const float*)d_in[8];
    const float* Wc       = (const float*)d_in[9];
    const float* bc       = (const float*)d_in[10];
    const float* W_proj   = (const float*)d_in[11];
    const float* b_proj   = (const float*)d_in[12];
    const float* W_out    = (const float*)d_in[13];
    const float* b_out    = (const float*)d_in[14];
    float* out = (float*)d_out;

    static_assert((MD * 128 + NT * 164 + 128) * 4 < 128 * 1024, "smem");
    size_t nu_smem = (size_t)(MD * 128 + NT * 164 + 128) * sizeof(float);
    cudaFuncSetAttribute(node_update_kernel,
                         cudaFuncAttributeMaxDynamicSharedMemorySize, (int)nu_smem);

    // prelude: zero accumulators; fused counts + attr scatter; inverses
    zero_prelude_kernel<<<1184, 256>>>();
    attr_scatter_kernel<<<(NI * 8) / 256, 256>>>(inod, ihed, attr);
    inv_kernel<<<(NH + 255) / 256, 256>>>();

    // embed (also zeroes hsum/nsum for layer 0)
    embed_kernel<<<592, 256>>>(x, W_embed, b_embed);

    // 3 message-passing layers (node_update re-zeroes accumulators for next layer)
    for (int l = 0; l < NL; l++) {
        scatter_n2h_kernel<<<(NI * 16) / 256, 256>>>(inod, ihed);
        scatter_h2n_kernel<<<(NI * 16) / 256, 256>>>(inod, ihed);
        node_update_kernel<<<296, 256, nu_smem>>>(Wf, bf, Wc, bc, l);
    }

    // pooling + head
    pool_kernel<<<(NN * 16) / 256, 256>>>(batch);
    head_kernel<<<NG, HOUT>>>(W_proj, b_proj, W_out, b_out, out);
}

// round 4
// speedup vs baseline: 1.3894x; 1.3894x over previous
#include <cuda_runtime.h>
#include <math.h>

#define NN   100000      // nodes
#define NI   2000000     // incidences
#define NH   300000      // hyperedges
#define IND  92          // input feature dim
#define HD   64          // hidden dim
#define AD   35          // hedge attr dim
#define ADP  36          // padded attr stride
#define HOUT 128
#define NG   512
#define NL   3
#define MD   163         // 2*HD + AD

#define NT   16          // nodes per GEMM tile
#define NTILES (NN / NT) // 6250 exactly

// CSR scan config
#define IPB  1024                      // items per scan block
#define NBH  ((NH + IPB - 1) / IPB)    // 293
#define NBN  ((NN + IPB - 1) / IPB)    // 98
#define NPART (NBH + NBN)              // 391

// ---------------- scratch (device globals; no allocation allowed) ------------
__device__ __align__(16) float g_h[NN * HD];       // node features (in-place updated)
__device__ __align__(16) float g_hsum[NH * HD];    // hedge means
__device__ __align__(16) float g_nsum[NN * HD];    // node means of hedge means
__device__ __align__(16) float g_na[NN * ADP];     // node attr means (padded)
__device__ __align__(16) float g_pool[NG * HD];
__device__ __align__(16) float g_pcnt[NG];

__device__ __align__(16) int g_cnt_h[NH];
__device__ __align__(16) int g_cnt_n[NN];
__device__ __align__(16) int g_off_h[NH];
__device__ __align__(16) int g_off_n[NN];
__device__ __align__(16) int g_cur_h[NH];
__device__ __align__(16) int g_cur_n[NN];
__device__ __align__(16) int g_csr_h[NI];          // node ids grouped by hedge
__device__ __align__(16) int g_csr_n[NI];          // hedge ids grouped by node
__device__ __align__(16) int g_part[512];

// ---------------- helpers ----------------------------------------------------
__device__ __forceinline__ void red_add_f4(float* a, float4 v) {
    asm volatile("red.global.add.v4.f32 [%0], {%1, %2, %3, %4};"
                 :: "l"(a), "f"(v.x), "f"(v.y), "f"(v.z), "f"(v.w) : "memory");
}
__device__ __forceinline__ void red_add_f1(float* a, float v) {
    asm volatile("red.global.add.f32 [%0], %1;" :: "l"(a), "f"(v) : "memory");
}
__device__ __forceinline__ float sigmoidf_(float x) {
    return 1.0f / (1.0f + __expf(-x));
}
__device__ __forceinline__ float softplusf_(float x) {
    if (x > 20.0f) return x;
    return log1pf(expf(x));
}

// ---------------- zero small buffers ------------------------------------------
__global__ void zero_small_kernel() {
    int stride = gridDim.x * blockDim.x;
    int t0 = blockIdx.x * blockDim.x + threadIdx.x;
    int4 zi = make_int4(0, 0, 0, 0);
    float4 zf = make_float4(0.f, 0.f, 0.f, 0.f);
    int4* ch = reinterpret_cast<int4*>(g_cnt_h);
    int4* cn = reinterpret_cast<int4*>(g_cnt_n);
    float4* pl = reinterpret_cast<float4*>(g_pool);
    float4* pc = reinterpret_cast<float4*>(g_pcnt);
    for (int i = t0; i < NH/4;    i += stride) ch[i] = zi;
    for (int i = t0; i < NN/4;    i += stride) cn[i] = zi;
    for (int i = t0; i < NG*HD/4; i += stride) pl[i] = zf;
    for (int i = t0; i < NG/4;    i += stride) pc[i] = zf;
}

// ---------------- counts ------------------------------------------------------
__global__ void count_kernel(const int* __restrict__ inod, const int* __restrict__ ihed) {
    int t = blockIdx.x * blockDim.x + threadIdx.x;
    if (t >= NI) return;
    atomicAdd(&g_cnt_h[ihed[t]], 1);
    atomicAdd(&g_cnt_n[inod[t]], 1);
}

// ---------------- scan phase 1: per-block exclusive offsets + partials --------
__global__ void scan_blocks_kernel() {
    __shared__ int ssum[256];
    int b = blockIdx.x;
    const int* cnt; int* off; int n, base;
    if (b < NBH) { cnt = g_cnt_h; off = g_off_h; n = NH; base = b * IPB; }
    else         { cnt = g_cnt_n; off = g_off_n; n = NN; base = (b - NBH) * IPB; }
    int tid = threadIdx.x;
    int i0 = base + tid * 4;
    int v0 = 0, v1 = 0, v2 = 0, v3 = 0;
    if (i0 + 3 < n) {
        int4 c = *reinterpret_cast<const int4*>(cnt + i0);
        v0 = c.x; v1 = c.y; v2 = c.z; v3 = c.w;
    } else {
        if (i0 + 0 < n) v0 = cnt[i0 + 0];
        if (i0 + 1 < n) v1 = cnt[i0 + 1];
        if (i0 + 2 < n) v2 = cnt[i0 + 2];
        if (i0 + 3 < n) v3 = cnt[i0 + 3];
    }
    int s = v0 + v1 + v2 + v3;
    ssum[tid] = s;
    __syncthreads();
    for (int o = 1; o < 256; o <<= 1) {
        int t = (tid >= o) ? ssum[tid - o] : 0;
        __syncthreads();
        ssum[tid] += t;
        __syncthreads();
    }
    int excl = ssum[tid] - s;
    if (tid == 255) g_part[b] = ssum[255];
    if (i0 + 0 < n) off[i0 + 0] = excl;
    if (i0 + 1 < n) off[i0 + 1] = excl + v0;
    if (i0 + 2 < n) off[i0 + 2] = excl + v0 + v1;
    if (i0 + 3 < n) off[i0 + 3] = excl + v0 + v1 + v2;
}

// ---------------- scan phase 2: scan the partials (single block) --------------
__global__ void scan_top_kernel() {
    __shared__ int sm[512];
    int tid = threadIdx.x;
    // hedge section [0, NBH)
    int v = (tid < NBH) ? g_part[tid] : 0;
    sm[tid] = v;
    __syncthreads();
    for (int o = 1; o < 512; o <<= 1) {
        int t = (tid >= o) ? sm[tid - o] : 0;
        __syncthreads();
        sm[tid] += t;
        __syncthreads();
    }
    if (tid < NBH) g_part[tid] = sm[tid] - v;
    __syncthreads();
    // node section [NBH, NBH+NBN)
    int v2 = (tid < NBN) ? g_part[NBH + tid] : 0;
    sm[tid] = v2;
    __syncthreads();
    for (int o = 1; o < 512; o <<= 1) {
        int t = (tid >= o) ? sm[tid - o] : 0;
        __syncthreads();
        sm[tid] += t;
        __syncthreads();
    }
    if (tid < NBN) g_part[NBH + tid] = sm[tid] - v2;
}

// ---------------- scan phase 3: add partials, init cursors --------------------
__global__ void scan_add_kernel() {
    int b = blockIdx.x;
    int* off; int* cur; int n, base;
    if (b < NBH) { off = g_off_h; cur = g_cur_h; n = NH; base = b * IPB; }
    else         { off = g_off_n; cur = g_cur_n; n = NN; base = (b - NBH) * IPB; }
    int add = g_part[b];
    int tid = threadIdx.x;
    int i0 = base + tid * 4;
    #pragma unroll
    for (int u = 0; u < 4; u++) {
        int i = i0 + u;
        if (i < n) { int o = off[i] + add; off[i] = o; cur[i] = o; }
    }
}

// ---------------- CSR fill ----------------------------------------------------
__global__ void fill_kernel(const int* __restrict__ inod, const int* __restrict__ ihed) {
    int t = blockIdx.x * blockDim.x + threadIdx.x;
    if (t >= NI) return;
    int nd = inod[t], he = ihed[t];
    int sh = atomicAdd(&g_cur_h[he], 1);
    g_csr_h[sh] = nd;
    int sn = atomicAdd(&g_cur_n[nd], 1);
    g_csr_n[sn] = he;
}

// ---------------- attr gather: node attr means (via node CSR) ----------------
// 16-lane group per node: lanes 0..7 handle float4 chunks (cols 0..31),
// lane 8 handles tail cols 32..34, lanes 9..15 idle.
__global__ void attr_gather_kernel(const float* __restrict__ attr) {
    int t = blockIdx.x * blockDim.x + threadIdx.x;
    if (t >= NN * 16) return;
    int node = t >> 4, c = t & 15;
    if (c > 8) return;
    int off = g_off_n[node], len = g_cnt_n[node];
    float inv = 1.0f / fmaxf((float)len, 1.0f);
    if (c < 8) {
        float4 acc = make_float4(0.f, 0.f, 0.f, 0.f);
        for (int s = 0; s < len; s++) {
            int he = __ldg(g_csr_n + off + s);
            const float* ap = attr + (size_t)he * AD + c * 4;
            acc.x += __ldg(ap);
            acc.y += __ldg(ap + 1);
            acc.z += __ldg(ap + 2);
            acc.w += __ldg(ap + 3);
        }
        acc.x *= inv; acc.y *= inv; acc.z *= inv; acc.w *= inv;
        *reinterpret_cast<float4*>(g_na + node * ADP + c * 4) = acc;
    } else {
        float a0 = 0.f, a1 = 0.f, a2 = 0.f;
        for (int s = 0; s < len; s++) {
            int he = __ldg(g_csr_n + off + s);
            const float* ap = attr + (size_t)he * AD + 32;
            a0 += __ldg(ap);
            a1 += __ldg(ap + 1);
            a2 += __ldg(ap + 2);
        }
        g_na[node * ADP + 32] = a0 * inv;
        g_na[node * ADP + 33] = a1 * inv;
        g_na[node * ADP + 34] = a2 * inv;
    }
}

// ---------------- embed GEMM: h = x @ W_embed + b ----------------------------
__global__ __launch_bounds__(256) void embed_kernel(const float* __restrict__ x,
                                                    const float* __restrict__ W,
                                                    const float* __restrict__ b) {
    __shared__ float Ws[IND * HD];
    __shared__ float bs[HD];
    __shared__ float xs[NT * IND];   // row stride 92 floats (368B, float4-aligned)
    int tid = threadIdx.x;
    for (int idx = tid; idx < IND * HD; idx += 256) Ws[idx] = W[idx];
    if (tid < HD) bs[tid] = b[tid];
    __syncthreads();

    int j = tid & 63, g = tid >> 6;  // g in 0..3, each handles 4 nodes
    for (int tile = blockIdx.x; tile < NTILES; tile += gridDim.x) {
        int base = tile * NT;
        {   // bulk float4 copy: NT*IND floats = 368 float4s
            const float4* src = reinterpret_cast<const float4*>(x + (size_t)base * IND);
            float4* dst = reinterpret_cast<float4*>(xs);
            for (int idx = tid; idx < NT * IND / 4; idx += 256) dst[idx] = src[idx];
        }
        __syncthreads();
        float a0 = 0.f, a1 = 0.f, a2 = 0.f, a3 = 0.f;
        int n0 = g * 4;
        const float4* x0p = reinterpret_cast<const float4*>(xs + (n0 + 0) * IND);
        const float4* x1p = reinterpret_cast<const float4*>(xs + (n0 + 1) * IND);
        const float4* x2p = reinterpret_cast<const float4*>(xs + (n0 + 2) * IND);
        const float4* x3p = reinterpret_cast<const float4*>(xs + (n0 + 3) * IND);
        #pragma unroll 4
        for (int kq = 0; kq < IND / 4; kq++) {
            float4 z0 = x0p[kq], z1 = x1p[kq], z2 = x2p[kq], z3 = x3p[kq];
            const float* wp = Ws + (kq * 4) * HD + j;
            { float w = wp[0];
              a0 += w * z0.x; a1 += w * z1.x; a2 += w * z2.x; a3 += w * z3.x; }
            { float w = wp[HD];
              a0 += w * z0.y; a1 += w * z1.y; a2 += w * z2.y; a3 += w * z3.y; }
            { float w = wp[2*HD];
              a0 += w * z0.z; a1 += w * z1.z; a2 += w * z2.z; a3 += w * z3.z; }
            { float w = wp[3*HD];
              a0 += w * z0.w; a1 += w * z1.w; a2 += w * z2.w; a3 += w * z3.w; }
        }
        float bb = bs[j];
        g_h[(base + n0 + 0) * HD + j] = a0 + bb;
        g_h[(base + n0 + 1) * HD + j] = a1 + bb;
        g_h[(base + n0 + 2) * HD + j] = a2 + bb;
        g_h[(base + n0 + 3) * HD + j] = a3 + bb;
        __syncthreads();
    }
}

// ---------------- gather node -> hedge mean ----------------------------------
// 16-lane group per hedge; lane c owns float4 columns c*4..c*4+3.
__global__ __launch_bounds__(256) void gather_n2h_kernel() {
    int t = blockIdx.x * blockDim.x + threadIdx.x;
    if (t >= NH * 16) return;
    int he = t >> 4, c = t & 15;
    int off = g_off_h[he], len = g_cnt_h[he];
    float4 acc = make_float4(0.f, 0.f, 0.f, 0.f);
    int s = 0;
    for (; s + 2 <= len; s += 2) {
        int nd0 = __ldg(g_csr_h + off + s);
        int nd1 = __ldg(g_csr_h + off + s + 1);
        float4 a = __ldg(reinterpret_cast<const float4*>(g_h + nd0 * HD + c * 4));
        float4 b = __ldg(reinterpret_cast<const float4*>(g_h + nd1 * HD + c * 4));
        acc.x += a.x + b.x; acc.y += a.y + b.y;
        acc.z += a.z + b.z; acc.w += a.w + b.w;
    }
    if (s < len) {
        int nd = __ldg(g_csr_h + off + s);
        float4 a = __ldg(reinterpret_cast<const float4*>(g_h + nd * HD + c * 4));
        acc.x += a.x; acc.y += a.y; acc.z += a.z; acc.w += a.w;
    }
    float inv = 1.0f / fmaxf((float)len, 1.0f);
    acc.x *= inv; acc.y *= inv; acc.z *= inv; acc.w *= inv;
    *reinterpret_cast<float4*>(g_hsum + he * HD + c * 4) = acc;
}

// ---------------- gather hedge -> node mean ----------------------------------
__global__ __launch_bounds__(256) void gather_h2n_kernel() {
    int t = blockIdx.x * blockDim.x + threadIdx.x;
    if (t >= NN * 16) return;
    int node = t >> 4, c = t & 15;
    int off = g_off_n[node], len = g_cnt_n[node];
    float4 acc = make_float4(0.f, 0.f, 0.f, 0.f);
    int s = 0;
    for (; s + 2 <= len; s += 2) {
        int he0 = __ldg(g_csr_n + off + s);
        int he1 = __ldg(g_csr_n + off + s + 1);
        float4 a = __ldg(reinterpret_cast<const float4*>(g_hsum + he0 * HD + c * 4));
        float4 b = __ldg(reinterpret_cast<const float4*>(g_hsum + he1 * HD + c * 4));
        acc.x += a.x + b.x; acc.y += a.y + b.y;
        acc.z += a.z + b.z; acc.w += a.w + b.w;
    }
    if (s < len) {
        int he = __ldg(g_csr_n + off + s);
        float4 a = __ldg(reinterpret_cast<const float4*>(g_hsum + he * HD + c * 4));
        acc.x += a.x; acc.y += a.y; acc.z += a.z; acc.w += a.w;
    }
    float inv = 1.0f / fmaxf((float)len, 1.0f);
    acc.x *= inv; acc.y *= inv; acc.z *= inv; acc.w *= inv;
    *reinterpret_cast<float4*>(g_nsum + node * HD + c * 4) = acc;
}

// ---------------- per-node update: z@[Wf|Wc] + gated softplus ----------------
// Dynamic smem: Wcat[163*128] + z[NT*164] + bf[64] + bc[64]
__global__ __launch_bounds__(256) void node_update_kernel(
        const float* __restrict__ Wf, const float* __restrict__ bf,
        const float* __restrict__ Wc, const float* __restrict__ bc, int layer) {
    extern __shared__ float sm[];
    float* Wsm = sm;                    // MD*128
    float* zs  = sm + MD * 128;         // NT*164
    float* bfs = zs + NT * 164;         // 64
    float* bcs = bfs + 64;              // 64

    const float* Wfl = Wf + (size_t)layer * MD * HD;
    const float* Wcl = Wc + (size_t)layer * MD * HD;
    int tid = threadIdx.x;
    for (int idx = tid; idx < MD * 128; idx += 256) {
        int k = idx >> 7, c = idx & 127;
        Wsm[idx] = (c < HD) ? Wfl[k * HD + c] : Wcl[k * HD + (c - HD)];
    }
    if (tid < HD) { bfs[tid] = bf[layer * HD + tid]; bcs[tid] = bc[layer * HD + tid]; }
    __syncthreads();

    int j = tid & 63, g = tid >> 6;     // g in 0..3, each handles 4 nodes
    for (int tile = blockIdx.x; tile < NTILES; tile += gridDim.x) {
        int base = tile * NT;
        // build z rows: [h*has | nsum (mean) | na (mean)]
        for (int idx = tid; idx < NT * MD; idx += 256) {
            int n = idx / MD, k = idx % MD;
            int node = base + n;
            float v;
            if (k < HD)        v = g_h[node * HD + k] * ((g_cnt_n[node] > 0) ? 1.0f : 0.0f);
            else if (k < 2*HD) v = g_nsum[node * HD + (k - HD)];
            else               v = g_na[node * ADP + (k - 2*HD)];
            zs[n * 164 + k] = v;
        }
        __syncthreads();

        float f0=0.f,f1=0.f,f2=0.f,f3=0.f, c0=0.f,c1=0.f,c2=0.f,c3=0.f;
        int n0 = g * 4;
        const float4* z0p = reinterpret_cast<const float4*>(zs + (n0 + 0) * 164);
        const float4* z1p = reinterpret_cast<const float4*>(zs + (n0 + 1) * 164);
        const float4* z2p = reinterpret_cast<const float4*>(zs + (n0 + 2) * 164);
        const float4* z3p = reinterpret_cast<const float4*>(zs + (n0 + 3) * 164);
        #pragma unroll 4
        for (int kq = 0; kq < MD / 4; kq++) {       // k = 0..159 in float4 chunks
            float4 z0 = z0p[kq], z1 = z1p[kq], z2 = z2p[kq], z3 = z3p[kq];
            const float* wp = Wsm + (kq * 4) * 128 + j;
            {
                float wf = wp[0], wc = wp[64];
                f0 += wf * z0.x; c0 += wc * z0.x;
                f1 += wf * z1.x; c1 += wc * z1.x;
                f2 += wf * z2.x; c2 += wc * z2.x;
                f3 += wf * z3.x; c3 += wc * z3.x;
            }
            {
                float wf = wp[128], wc = wp[192];
                f0 += wf * z0.y; c0 += wc * z0.y;
                f1 += wf * z1.y; c1 += wc * z1.y;
                f2 += wf * z2.y; c2 += wc * z2.y;
                f3 += wf * z3.y; c3 += wc * z3.y;
            }
            {
                float wf = wp[256], wc = wp[320];
                f0 += wf * z0.z; c0 += wc * z0.z;
                f1 += wf * z1.z; c1 += wc * z1.z;
                f2 += wf * z2.z; c2 += wc * z2.z;
                f3 += wf * z3.z; c3 += wc * z3.z;
            }
            {
                float wf = wp[384], wc = wp[448];
                f0 += wf * z0.w; c0 += wc * z0.w;
                f1 += wf * z1.w; c1 += wc * z1.w;
                f2 += wf * z2.w; c2 += wc * z2.w;
                f3 += wf * z3.w; c3 += wc * z3.w;
            }
        }
        // tail k = 160..162
        #pragma unroll
        for (int k = (MD / 4) * 4; k < MD; k++) {
            float wf = Wsm[k * 128 + j];
            float wc = Wsm[k * 128 + j + 64];
            float z0 = zs[(n0 + 0) * 164 + k], z1 = zs[(n0 + 1) * 164 + k];
            float z2 = zs[(n0 + 2) * 164 + k], z3 = zs[(n0 + 3) * 164 + k];
            f0 += wf * z0; c0 += wc * z0;
            f1 += wf * z1; c1 += wc * z1;
            f2 += wf * z2; c2 += wc * z2;
            f3 += wf * z3; c3 += wc * z3;
        }
        float bfv = bfs[j], bcv = bcs[j];
        {
            int node = base + n0 + 0; float h = g_h[node * HD + j];
            g_h[node * HD + j] = softplusf_(sigmoidf_(f0 + bfv) * softplusf_(c0 + bcv) + h);
        }
        {
            int node = base + n0 + 1; float h = g_h[node * HD + j];
            g_h[node * HD + j] = softplusf_(sigmoidf_(f1 + bfv) * softplusf_(c1 + bcv) + h);
        }
        {
            int node = base + n0 + 2; float h = g_h[node * HD + j];
            g_h[node * HD + j] = softplusf_(sigmoidf_(f2 + bfv) * softplusf_(c2 + bcv) + h);
        }
        {
            int node = base + n0 + 3; float h = g_h[node * HD + j];
            g_h[node * HD + j] = softplusf_(sigmoidf_(f3 + bfv) * softplusf_(c3 + bcv) + h);
        }
        __syncthreads();
    }
}

// ---------------- pooling scatter (small; atomics fine) ----------------------
__global__ void pool_kernel(const int* __restrict__ batch) {
    int t = blockIdx.x * blockDim.x + threadIdx.x;
    if (t >= NN * 16) return;
    int i = t >> 4, c = t & 15;
    int gidx = batch[i];
    float4 v = __ldg(reinterpret_cast<const float4*>(g_h + i * HD + c * 4));
    red_add_f4(g_pool + gidx * HD + c * 4, v);
    if (c == 0) red_add_f1(g_pcnt + gidx, 1.0f);
}

// ---------------- head: softplus(pool@Wp + bp) @ Wo + bo ---------------------
__global__ void head_kernel(const float* __restrict__ Wp, const float* __restrict__ bp,
                            const float* __restrict__ Wo, const float* __restrict__ bo,
                            float* __restrict__ out) {
    __shared__ float ps[HD];
    __shared__ float rbuf[4];
    int g = blockIdx.x, tid = threadIdx.x;
    if (tid < HD)
        ps[tid] = g_pool[g * HD + tid] * (1.0f / fmaxf(g_pcnt[g], 1.0f));
    __syncthreads();
    float acc = bp[tid];
    #pragma unroll
    for (int k = 0; k < HD; k++) acc += ps[k] * Wp[k * HOUT + tid];
    float val = softplusf_(acc) * Wo[tid];
    #pragma unroll
    for (int o = 16; o; o >>= 1) val += __shfl_down_sync(0xffffffffu, val, o);
    if ((tid & 31) == 0) rbuf[tid >> 5] = val;
    __syncthreads();
    if (tid == 0) out[g] = rbuf[0] + rbuf[1] + rbuf[2] + rbuf[3] + bo[0];
}

// ---------------- launch ------------------------------------------------------
extern "C" void kernel_launch(void* const* d_in, const int* in_sizes, int n_in,
                              void* d_out, int out_size) {
    const float* x        = (const float*)d_in[0];
    const int*   inod     = (const int*)  d_in[1];
    const int*   ihed     = (const int*)  d_in[2];
    const float* attr     = (const float*)d_in[3];
    const int*   batch    = (const int*)  d_in[4];
    const float* W_embed  = (const float*)d_in[5];
    const float* b_embed  = (const float*)d_in[6];
    const float* Wf       = (const float*)d_in[7];
    const float* bf       = (const float*)d_in[8];
    const float* Wc       = (const float*)d_in[9];
    const float* bc       = (const float*)d_in[10];
    const float* W_proj   = (const float*)d_in[11];
    const float* b_proj   = (const float*)d_in[12];
    const float* W_out    = (const float*)d_in[13];
    const float* b_out    = (const float*)d_in[14];
    float* out = (float*)d_out;

    static_assert((MD * 128 + NT * 164 + 128) * 4 < 128 * 1024, "smem");
    size_t nu_smem = (size_t)(MD * 128 + NT * 164 + 128) * sizeof(float);
    cudaFuncSetAttribute(node_update_kernel,
                         cudaFuncAttributeMaxDynamicSharedMemorySize, (int)nu_smem);

    // --- CSR build ---
    zero_small_kernel<<<256, 256>>>();
    count_kernel<<<(NI + 255) / 256, 256>>>(inod, ihed);
    scan_blocks_kernel<<<NPART, 256>>>();
    scan_top_kernel<<<1, 512>>>();
    scan_add_kernel<<<NPART, 256>>>();
    fill_kernel<<<(NI + 255) / 256, 256>>>(inod, ihed);

    // --- layer-invariant node attr means + embed ---
    attr_gather_kernel<<<(NN * 16) / 256, 256>>>(attr);
    embed_kernel<<<592, 256>>>(x, W_embed, b_embed);

    // --- 3 message-passing layers ---
    for (int l = 0; l < NL; l++) {
        gather_n2h_kernel<<<(NH * 16) / 256, 256>>>();
        gather_h2n_kernel<<<(NN * 16) / 256, 256>>>();
        node_update_kernel<<<296, 256, nu_smem>>>(Wf, bf, Wc, bc, l);
    }

    // --- pooling + head ---
    pool_kernel<<<(NN * 16) / 256, 256>>>(batch);
    head_kernel<<<NG, HOUT>>>(W_proj, b_proj, W_out, b_out, out);
}

// round 15
// speedup vs baseline: 1.3966x; 1.0052x over previous
#include <cuda_runtime.h>
#include <math.h>

#define NN   100000      // nodes
#define NI   2000000     // incidences
#define NH   300000      // hyperedges
#define IND  92          // input feature dim
#define HD   64          // hidden dim
#define AD   35          // hedge attr dim
#define ADP  36          // padded attr stride
#define HOUT 128
#define NG   512
#define NL   3
#define MD   163         // 2*HD + AD

#define NT   16          // nodes per GEMM tile
#define NTILES (NN / NT) // 6250 exactly

// CSR scan config
#define IPB  1024                      // items per scan block
#define NBH  ((NH + IPB - 1) / IPB)    // 293
#define NBN  ((NN + IPB - 1) / IPB)    // 98
#define NPART (NBH + NBN)              // 391

// ---------------- scratch (device globals; no allocation allowed) ------------
__device__ __align__(16) float g_h[NN * HD];       // node features (in-place updated)
__device__ __align__(16) float g_hsum[NH * HD];    // hedge means
__device__ __align__(16) float g_nsum[NN * HD];    // node means of hedge means
__device__ __align__(16) float g_na[NN * ADP];     // node attr means (padded)
__device__ __align__(16) float g_pool[NG * HD];
__device__ __align__(16) float g_pcnt[NG];

__device__ __align__(16) int g_cnt_h[NH];
__device__ __align__(16) int g_cnt_n[NN];
__device__ __align__(16) int g_off_h[NH];
__device__ __align__(16) int g_off_n[NN];
__device__ __align__(16) int g_cur_h[NH];
__device__ __align__(16) int g_cur_n[NN];
__device__ __align__(16) int g_csr_h[NI];          // node ids grouped by hedge
__device__ __align__(16) int g_csr_n[NI];          // hedge ids grouped by node
__device__ __align__(16) int g_part[512];

// ---------------- helpers ----------------------------------------------------
__device__ __forceinline__ void red_add_f4(float* a, float4 v) {
    asm volatile("red.global.add.v4.f32 [%0], {%1, %2, %3, %4};"
                 :: "l"(a), "f"(v.x), "f"(v.y), "f"(v.z), "f"(v.w) : "memory");
}
__device__ __forceinline__ void red_add_f1(float* a, float v) {
    asm volatile("red.global.add.f32 [%0], %1;" :: "l"(a), "f"(v) : "memory");
}
__device__ __forceinline__ float sigmoidf_(float x) {
    return 1.0f / (1.0f + __expf(-x));
}
__device__ __forceinline__ float softplusf_(float x) {
    if (x > 20.0f) return x;
    return log1pf(expf(x));
}

// ---------------- zero small buffers ------------------------------------------
__global__ void zero_small_kernel() {
    int stride = gridDim.x * blockDim.x;
    int t0 = blockIdx.x * blockDim.x + threadIdx.x;
    int4 zi = make_int4(0, 0, 0, 0);
    float4 zf = make_float4(0.f, 0.f, 0.f, 0.f);
    int4* ch = reinterpret_cast<int4*>(g_cnt_h);
    int4* cn = reinterpret_cast<int4*>(g_cnt_n);
    float4* pl = reinterpret_cast<float4*>(g_pool);
    float4* pc = reinterpret_cast<float4*>(g_pcnt);
    for (int i = t0; i < NH/4;    i += stride) ch[i] = zi;
    for (int i = t0; i < NN/4;    i += stride) cn[i] = zi;
    for (int i = t0; i < NG*HD/4; i += stride) pl[i] = zf;
    for (int i = t0; i < NG/4;    i += stride) pc[i] = zf;
}

// ---------------- counts ------------------------------------------------------
__global__ void count_kernel(const int* __restrict__ inod, const int* __restrict__ ihed) {
    int t = blockIdx.x * blockDim.x + threadIdx.x;
    if (t >= NI) return;
    atomicAdd(&g_cnt_h[ihed[t]], 1);
    atomicAdd(&g_cnt_n[inod[t]], 1);
}

// ---------------- scan phase 1: per-block exclusive offsets + partials --------
__global__ void scan_blocks_kernel() {
    __shared__ int ssum[256];
    int b = blockIdx.x;
    const int* cnt; int* off; int n, base;
    if (b < NBH) { cnt = g_cnt_h; off = g_off_h; n = NH; base = b * IPB; }
    else         { cnt = g_cnt_n; off = g_off_n; n = NN; base = (b - NBH) * IPB; }
    int tid = threadIdx.x;
    int i0 = base + tid * 4;
    int v0 = 0, v1 = 0, v2 = 0, v3 = 0;
    if (i0 + 3 < n) {
        int4 c = *reinterpret_cast<const int4*>(cnt + i0);
        v0 = c.x; v1 = c.y; v2 = c.z; v3 = c.w;
    } else {
        if (i0 + 0 < n) v0 = cnt[i0 + 0];
        if (i0 + 1 < n) v1 = cnt[i0 + 1];
        if (i0 + 2 < n) v2 = cnt[i0 + 2];
        if (i0 + 3 < n) v3 = cnt[i0 + 3];
    }
    int s = v0 + v1 + v2 + v3;
    ssum[tid] = s;
    __syncthreads();
    for (int o = 1; o < 256; o <<= 1) {
        int t = (tid >= o) ? ssum[tid - o] : 0;
        __syncthreads();
        ssum[tid] += t;
        __syncthreads();
    }
    int excl = ssum[tid] - s;
    if (tid == 255) g_part[b] = ssum[255];
    if (i0 + 0 < n) off[i0 + 0] = excl;
    if (i0 + 1 < n) off[i0 + 1] = excl + v0;
    if (i0 + 2 < n) off[i0 + 2] = excl + v0 + v1;
    if (i0 + 3 < n) off[i0 + 3] = excl + v0 + v1 + v2;
}

// ---------------- scan phase 2: scan the partials (single block) --------------
__global__ void scan_top_kernel() {
    __shared__ int sm[512];
    int tid = threadIdx.x;
    int v = (tid < NBH) ? g_part[tid] : 0;
    sm[tid] = v;
    __syncthreads();
    for (int o = 1; o < 512; o <<= 1) {
        int t = (tid >= o) ? sm[tid - o] : 0;
        __syncthreads();
        sm[tid] += t;
        __syncthreads();
    }
    if (tid < NBH) g_part[tid] = sm[tid] - v;
    __syncthreads();
    int v2 = (tid < NBN) ? g_part[NBH + tid] : 0;
    sm[tid] = v2;
    __syncthreads();
    for (int o = 1; o < 512; o <<= 1) {
        int t = (tid >= o) ? sm[tid - o] : 0;
        __syncthreads();
        sm[tid] += t;
        __syncthreads();
    }
    if (tid < NBN) g_part[NBH + tid] = sm[tid] - v2;
}

// ---------------- scan phase 3: add partials, init cursors --------------------
__global__ void scan_add_kernel() {
    int b = blockIdx.x;
    int* off; int* cur; int n, base;
    if (b < NBH) { off = g_off_h; cur = g_cur_h; n = NH; base = b * IPB; }
    else         { off = g_off_n; cur = g_cur_n; n = NN; base = (b - NBH) * IPB; }
    int add = g_part[b];
    int tid = threadIdx.x;
    int i0 = base + tid * 4;
    #pragma unroll
    for (int u = 0; u < 4; u++) {
        int i = i0 + u;
        if (i < n) { int o = off[i] + add; off[i] = o; cur[i] = o; }
    }
}

// ---------------- CSR fill ----------------------------------------------------
__global__ void fill_kernel(const int* __restrict__ inod, const int* __restrict__ ihed) {
    int t = blockIdx.x * blockDim.x + threadIdx.x;
    if (t >= NI) return;
    int nd = inod[t], he = ihed[t];
    int sh = atomicAdd(&g_cur_h[he], 1);
    g_csr_h[sh] = nd;
    int sn = atomicAdd(&g_cur_n[nd], 1);
    g_csr_n[sn] = he;
}

// ---------------- attr gather: node attr means (via node CSR) ----------------
// 16-lane group per node: lanes 0..7 handle float4 chunks (cols 0..31),
// lane 8 handles tail cols 32..34, lanes 9..15 idle.
// 8-deep index-prefetch unroll (avg node degree ~20).
__global__ void attr_gather_kernel(const float* __restrict__ attr) {
    int t = blockIdx.x * blockDim.x + threadIdx.x;
    if (t >= NN * 16) return;
    int node = t >> 4, c = t & 15;
    if (c > 8) return;
    int off = g_off_n[node], len = g_cnt_n[node];
    float inv = 1.0f / fmaxf((float)len, 1.0f);
    if (c < 8) {
        float4 acc = make_float4(0.f, 0.f, 0.f, 0.f);
        int s = 0;
        for (; s + 8 <= len; s += 8) {
            int hx[8];
            #pragma unroll
            for (int u = 0; u < 8; u++) hx[u] = __ldg(g_csr_n + off + s + u);
            const float* ap[8];
            #pragma unroll
            for (int u = 0; u < 8; u++) ap[u] = attr + (size_t)hx[u] * AD + c * 4;
            #pragma unroll
            for (int u = 0; u < 8; u++) {
                acc.x += __ldg(ap[u]);
                acc.y += __ldg(ap[u] + 1);
                acc.z += __ldg(ap[u] + 2);
                acc.w += __ldg(ap[u] + 3);
            }
        }
        for (; s + 4 <= len; s += 4) {
            int h0 = __ldg(g_csr_n + off + s);
            int h1 = __ldg(g_csr_n + off + s + 1);
            int h2 = __ldg(g_csr_n + off + s + 2);
            int h3 = __ldg(g_csr_n + off + s + 3);
            const float* a0 = attr + (size_t)h0 * AD + c * 4;
            const float* a1 = attr + (size_t)h1 * AD + c * 4;
            const float* a2 = attr + (size_t)h2 * AD + c * 4;
            const float* a3 = attr + (size_t)h3 * AD + c * 4;
            acc.x += __ldg(a0) + __ldg(a1) + __ldg(a2) + __ldg(a3);
            acc.y += __ldg(a0+1) + __ldg(a1+1) + __ldg(a2+1) + __ldg(a3+1);
            acc.z += __ldg(a0+2) + __ldg(a1+2) + __ldg(a2+2) + __ldg(a3+2);
            acc.w += __ldg(a0+3) + __ldg(a1+3) + __ldg(a2+3) + __ldg(a3+3);
        }
        for (; s < len; s++) {
            int he = __ldg(g_csr_n + off + s);
            const float* ap = attr + (size_t)he * AD + c * 4;
            acc.x += __ldg(ap);
            acc.y += __ldg(ap + 1);
            acc.z += __ldg(ap + 2);
            acc.w += __ldg(ap + 3);
        }
        acc.x *= inv; acc.y *= inv; acc.z *= inv; acc.w *= inv;
        *reinterpret_cast<float4*>(g_na + node * ADP + c * 4) = acc;
    } else {
        float a0 = 0.f, a1 = 0.f, a2 = 0.f;
        int s = 0;
        for (; s + 4 <= len; s += 4) {
            int h0 = __ldg(g_csr_n + off + s);
            int h1 = __ldg(g_csr_n + off + s + 1);
            int h2 = __ldg(g_csr_n + off + s + 2);
            int h3 = __ldg(g_csr_n + off + s + 3);
            const float* p0 = attr + (size_t)h0 * AD + 32;
            const float* p1 = attr + (size_t)h1 * AD + 32;
            const float* p2 = attr + (size_t)h2 * AD + 32;
            const float* p3 = attr + (size_t)h3 * AD + 32;
            a0 += (__ldg(p0) + __ldg(p1)) + (__ldg(p2) + __ldg(p3));
            a1 += (__ldg(p0+1) + __ldg(p1+1)) + (__ldg(p2+1) + __ldg(p3+1));
            a2 += (__ldg(p0+2) + __ldg(p1+2)) + (__ldg(p2+2) + __ldg(p3+2));
        }
        for (; s < len; s++) {
            int he = __ldg(g_csr_n + off + s);
            const float* ap = attr + (size_t)he * AD + 32;
            a0 += __ldg(ap); a1 += __ldg(ap + 1); a2 += __ldg(ap + 2);
        }
        g_na[node * ADP + 32] = a0 * inv;
        g_na[node * ADP + 33] = a1 * inv;
        g_na[node * ADP + 34] = a2 * inv;
    }
}

// ---------------- embed GEMM: h = x @ W_embed + b ----------------------------
__global__ __launch_bounds__(256) void embed_kernel(const float* __restrict__ x,
                                                    const float* __restrict__ W,
                                                    const float* __restrict__ b) {
    __shared__ float Ws[IND * HD];
    __shared__ float bs[HD];
    __shared__ float xs[NT * IND];
    int tid = threadIdx.x;
    for (int idx = tid; idx < IND * HD; idx += 256) Ws[idx] = W[idx];
    if (tid < HD) bs[tid] = b[tid];
    __syncthreads();

    int j = tid & 63, g = tid >> 6;
    for (int tile = blockIdx.x; tile < NTILES; tile += gridDim.x) {
        int base = tile * NT;
        {
            const float4* src = reinterpret_cast<const float4*>(x + (size_t)base * IND);
            float4* dst = reinterpret_cast<float4*>(xs);
            for (int idx = tid; idx < NT * IND / 4; idx += 256) dst[idx] = src[idx];
        }
        __syncthreads();
        float a0 = 0.f, a1 = 0.f, a2 = 0.f, a3 = 0.f;
        int n0 = g * 4;
        const float4* x0p = reinterpret_cast<const float4*>(xs + (n0 + 0) * IND);
        const float4* x1p = reinterpret_cast<const float4*>(xs + (n0 + 1) * IND);
        const float4* x2p = reinterpret_cast<const float4*>(xs + (n0 + 2) * IND);
        const float4* x3p = reinterpret_cast<const float4*>(xs + (n0 + 3) * IND);
        #pragma unroll 4
        for (int kq = 0; kq < IND / 4; kq++) {
            float4 z0 = x0p[kq], z1 = x1p[kq], z2 = x2p[kq], z3 = x3p[kq];
            const float* wp = Ws + (kq * 4) * HD + j;
            { float w = wp[0];
              a0 += w * z0.x; a1 += w * z1.x; a2 += w * z2.x; a3 += w * z3.x; }
            { float w = wp[HD];
              a0 += w * z0.y; a1 += w * z1.y; a2 += w * z2.y; a3 += w * z3.y; }
            { float w = wp[2*HD];
              a0 += w * z0.z; a1 += w * z1.z; a2 += w * z2.z; a3 += w * z3.z; }
            { float w = wp[3*HD];
              a0 += w * z0.w; a1 += w * z1.w; a2 += w * z2.w; a3 += w * z3.w; }
        }
        float bb = bs[j];
        g_h[(base + n0 + 0) * HD + j] = a0 + bb;
        g_h[(base + n0 + 1) * HD + j] = a1 + bb;
        g_h[(base + n0 + 2) * HD + j] = a2 + bb;
        g_h[(base + n0 + 3) * HD + j] = a3 + bb;
        __syncthreads();
    }
}

// ---------------- gather node -> hedge mean ----------------------------------
// 16-lane group per hedge; lane c owns float4 columns c*4..c*4+3.
// 4-way index-prefetch unroll (avg hedge degree ~6.7).
__global__ __launch_bounds__(256) void gather_n2h_kernel() {
    int t = blockIdx.x * blockDim.x + threadIdx.x;
    if (t >= NH * 16) return;
    int he = t >> 4, c = t & 15;
    int off = g_off_h[he], len = g_cnt_h[he];
    float4 acc = make_float4(0.f, 0.f, 0.f, 0.f);
    int s = 0;
    for (; s + 4 <= len; s += 4) {
        int n0 = __ldg(g_csr_h + off + s);
        int n1 = __ldg(g_csr_h + off + s + 1);
        int n2 = __ldg(g_csr_h + off + s + 2);
        int n3 = __ldg(g_csr_h + off + s + 3);
        float4 a = __ldg(reinterpret_cast<const float4*>(g_h + n0 * HD + c * 4));
        float4 b = __ldg(reinterpret_cast<const float4*>(g_h + n1 * HD + c * 4));
        float4 d = __ldg(reinterpret_cast<const float4*>(g_h + n2 * HD + c * 4));
        float4 e = __ldg(reinterpret_cast<const float4*>(g_h + n3 * HD + c * 4));
        acc.x += (a.x + b.x) + (d.x + e.x);
        acc.y += (a.y + b.y) + (d.y + e.y);
        acc.z += (a.z + b.z) + (d.z + e.z);
        acc.w += (a.w + b.w) + (d.w + e.w);
    }
    for (; s < len; s++) {
        int nd = __ldg(g_csr_h + off + s);
        float4 a = __ldg(reinterpret_cast<const float4*>(g_h + nd * HD + c * 4));
        acc.x += a.x; acc.y += a.y; acc.z += a.z; acc.w += a.w;
    }
    float inv = 1.0f / fmaxf((float)len, 1.0f);
    acc.x *= inv; acc.y *= inv; acc.z *= inv; acc.w *= inv;
    *reinterpret_cast<float4*>(g_hsum + he * HD + c * 4) = acc;
}

// ---------------- gather hedge -> node mean ----------------------------------
// 8-deep index-prefetch unroll (avg node degree ~20).
__global__ __launch_bounds__(256) void gather_h2n_kernel() {
    int t = blockIdx.x * blockDim.x + threadIdx.x;
    if (t >= NN * 16) return;
    int node = t >> 4, c = t & 15;
    int off = g_off_n[node], len = g_cnt_n[node];
    float4 acc = make_float4(0.f, 0.f, 0.f, 0.f);
    int s = 0;
    for (; s + 8 <= len; s += 8) {
        int hx[8];
        #pragma unroll
        for (int u = 0; u < 8; u++) hx[u] = __ldg(g_csr_n + off + s + u);
        float4 v[8];
        #pragma unroll
        for (int u = 0; u < 8; u++)
            v[u] = __ldg(reinterpret_cast<const float4*>(g_hsum + hx[u] * HD + c * 4));
        #pragma unroll
        for (int u = 0; u < 8; u++) {
            acc.x += v[u].x; acc.y += v[u].y; acc.z += v[u].z; acc.w += v[u].w;
        }
    }
    for (; s + 4 <= len; s += 4) {
        int h0 = __ldg(g_csr_n + off + s);
        int h1 = __ldg(g_csr_n + off + s + 1);
        int h2 = __ldg(g_csr_n + off + s + 2);
        int h3 = __ldg(g_csr_n + off + s + 3);
        float4 a = __ldg(reinterpret_cast<const float4*>(g_hsum + h0 * HD + c * 4));
        float4 b = __ldg(reinterpret_cast<const float4*>(g_hsum + h1 * HD + c * 4));
        float4 d = __ldg(reinterpret_cast<const float4*>(g_hsum + h2 * HD + c * 4));
        float4 e = __ldg(reinterpret_cast<const float4*>(g_hsum + h3 * HD + c * 4));
        acc.x += (a.x + b.x) + (d.x + e.x);
        acc.y += (a.y + b.y) + (d.y + e.y);
        acc.z += (a.z + b.z) + (d.z + e.z);
        acc.w += (a.w + b.w) + (d.w + e.w);
    }
    for (; s < len; s++) {
        int he = __ldg(g_csr_n + off + s);
        float4 a = __ldg(reinterpret_cast<const float4*>(g_hsum + he * HD + c * 4));
        acc.x += a.x; acc.y += a.y; acc.z += a.z; acc.w += a.w;
    }
    float inv = 1.0f / fmaxf((float)len, 1.0f);
    acc.x *= inv; acc.y *= inv; acc.z *= inv; acc.w *= inv;
    *reinterpret_cast<float4*>(g_nsum + node * HD + c * 4) = acc;
}

// ---------------- per-node update: z@[Wf|Wc] + gated softplus ----------------
__global__ __launch_bounds__(256) void node_update_kernel(
        const float* __restrict__ Wf, const float* __restrict__ bf,
        const float* __restrict__ Wc, const float* __restrict__ bc, int layer) {
    extern __shared__ float sm[];
    float* Wsm = sm;                    // MD*128
    float* zs  = sm + MD * 128;         // NT*164
    float* bfs = zs + NT * 164;         // 64
    float* bcs = bfs + 64;              // 64

    const float* Wfl = Wf + (size_t)layer * MD * HD;
    const float* Wcl = Wc + (size_t)layer * MD * HD;
    int tid = threadIdx.x;
    for (int idx = tid; idx < MD * 128; idx += 256) {
        int k = idx >> 7, c = idx & 127;
        Wsm[idx] = (c < HD) ? Wfl[k * HD + c] : Wcl[k * HD + (c - HD)];
    }
    if (tid < HD) { bfs[tid] = bf[layer * HD + tid]; bcs[tid] = bc[layer * HD + tid]; }
    __syncthreads();

    int j = tid & 63, g = tid >> 6;
    for (int tile = blockIdx.x; tile < NTILES; tile += gridDim.x) {
        int base = tile * NT;
        for (int idx = tid; idx < NT * MD; idx += 256) {
            int n = idx / MD, k = idx % MD;
            int node = base + n;
            float v;
            if (k < HD)        v = g_h[node * HD + k] * ((g_cnt_n[node] > 0) ? 1.0f : 0.0f);
            else if (k < 2*HD) v = g_nsum[node * HD + (k - HD)];
            else               v = g_na[node * ADP + (k - 2*HD)];
            zs[n * 164 + k] = v;
        }
        __syncthreads();

        float f0=0.f,f1=0.f,f2=0.f,f3=0.f, c0=0.f,c1=0.f,c2=0.f,c3=0.f;
        int n0 = g * 4;
        const float4* z0p = reinterpret_cast<const float4*>(zs + (n0 + 0) * 164);
        const float4* z1p = reinterpret_cast<const float4*>(zs + (n0 + 1) * 164);
        const float4* z2p = reinterpret_cast<const float4*>(zs + (n0 + 2) * 164);
        const float4* z3p = reinterpret_cast<const float4*>(zs + (n0 + 3) * 164);
        #pragma unroll 4
        for (int kq = 0; kq < MD / 4; kq++) {
            float4 z0 = z0p[kq], z1 = z1p[kq], z2 = z2p[kq], z3 = z3p[kq];
            const float* wp = Wsm + (kq * 4) * 128 + j;
            {
                float wf = wp[0], wc = wp[64];
                f0 += wf * z0.x; c0 += wc * z0.x;
                f1 += wf * z1.x; c1 += wc * z1.x;
                f2 += wf * z2.x; c2 += wc * z2.x;
                f3 += wf * z3.x; c3 += wc * z3.x;
            }
            {
                float wf = wp[128], wc = wp[192];
                f0 += wf * z0.y; c0 += wc * z0.y;
                f1 += wf * z1.y; c1 += wc * z1.y;
                f2 += wf * z2.y; c2 += wc * z2.y;
                f3 += wf * z3.y; c3 += wc * z3.y;
            }
            {
                float wf = wp[256], wc = wp[320];
                f0 += wf * z0.z; c0 += wc * z0.z;
                f1 += wf * z1.z; c1 += wc * z1.z;
                f2 += wf * z2.z; c2 += wc * z2.z;
                f3 += wf * z3.z; c3 += wc * z3.z;
            }
            {
                float wf = wp[384], wc = wp[448];
                f0 += wf * z0.w; c0 += wc * z0.w;
                f1 += wf * z1.w; c1 += wc * z1.w;
                f2 += wf * z2.w; c2 += wc * z2.w;
                f3 += wf * z3.w; c3 += wc * z3.w;
            }
        }
        #pragma unroll
        for (int k = (MD / 4) * 4; k < MD; k++) {
            float wf = Wsm[k * 128 + j];
            float wc = Wsm[k * 128 + j + 64];
            float z0 = zs[(n0 + 0) * 164 + k], z1 = zs[(n0 + 1) * 164 + k];
            float z2 = zs[(n0 + 2) * 164 + k], z3 = zs[(n0 + 3) * 164 + k];
            f0 += wf * z0; c0 += wc * z0;
            f1 += wf * z1; c1 += wc * z1;
            f2 += wf * z2; c2 += wc * z2;
            f3 += wf * z3; c3 += wc * z3;
        }
        float bfv = bfs[j], bcv = bcs[j];
        {
            int node = base + n0 + 0; float h = g_h[node * HD + j];
            g_h[node * HD + j] = softplusf_(sigmoidf_(f0 + bfv) * softplusf_(c0 + bcv) + h);
        }
        {
            int node = base + n0 + 1; float h = g_h[node * HD + j];
            g_h[node * HD + j] = softplusf_(sigmoidf_(f1 + bfv) * softplusf_(c1 + bcv) + h);
        }
        {
            int node = base + n0 + 2; float h = g_h[node * HD + j];
            g_h[node * HD + j] = softplusf_(sigmoidf_(f2 + bfv) * softplusf_(c2 + bcv) + h);
        }
        {
            int node = base + n0 + 3; float h = g_h[node * HD + j];
            g_h[node * HD + j] = softplusf_(sigmoidf_(f3 + bfv) * softplusf_(c3 + bcv) + h);
        }
        __syncthreads();
    }
}

// ---------------- pooling scatter (small; atomics fine) ----------------------
__global__ void pool_kernel(const int* __restrict__ batch) {
    int t = blockIdx.x * blockDim.x + threadIdx.x;
    if (t >= NN * 16) return;
    int i = t >> 4, c = t & 15;
    int gidx = batch[i];
    float4 v = __ldg(reinterpret_cast<const float4*>(g_h + i * HD + c * 4));
    red_add_f4(g_pool + gidx * HD + c * 4, v);
    if (c == 0) red_add_f1(g_pcnt + gidx, 1.0f);
}

// ---------------- head: softplus(pool@Wp + bp) @ Wo + bo ---------------------
__global__ void head_kernel(const float* __restrict__ Wp, const float* __restrict__ bp,
                            const float* __restrict__ Wo, const float* __restrict__ bo,
                            float* __restrict__ out) {
    __shared__ float ps[HD];
    __shared__ float rbuf[4];
    int g = blockIdx.x, tid = threadIdx.x;
    if (tid < HD)
        ps[tid] = g_pool[g * HD + tid] * (1.0f / fmaxf(g_pcnt[g], 1.0f));
    __syncthreads();
    float acc = bp[tid];
    #pragma unroll
    for (int k = 0; k < HD; k++) acc += ps[k] * Wp[k * HOUT + tid];
    float val = softplusf_(acc) * Wo[tid];
    #pragma unroll
    for (int o = 16; o; o >>= 1) val += __shfl_down_sync(0xffffffffu, val, o);
    if ((tid & 31) == 0) rbuf[tid >> 5] = val;
    __syncthreads();
    if (tid == 0) out[g] = rbuf[0] + rbuf[1] + rbuf[2] + rbuf[3] + bo[0];
}

// ---------------- launch ------------------------------------------------------
extern "C" void kernel_launch(void* const* d_in, const int* in_sizes, int n_in,
                              void* d_out, int out_size) {
    const float* x        = (const float*)d_in[0];
    const int*   inod     = (const int*)  d_in[1];
    const int*   ihed     = (const int*)  d_in[2];
    const float* attr     = (const float*)d_in[3];
    const int*   batch    = (const int*)  d_in[4];
    const float* W_embed  = (const float*)d_in[5];
    const float* b_embed  = (const float*)d_in[6];
    const float* Wf       = (const float*)d_in[7];
    const float* bf       = (const float*)d_in[8];
    const float* Wc       = (const float*)d_in[9];
    const float* bc       = (const float*)d_in[10];
    const float* W_proj   = (const float*)d_in[11];
    const float* b_proj   = (const float*)d_in[12];
    const float* W_out    = (const float*)d_in[13];
    const float* b_out    = (const float*)d_in[14];
    float* out = (float*)d_out;

    static_assert((MD * 128 + NT * 164 + 128) * 4 < 128 * 1024, "smem");
    size_t nu_smem = (size_t)(MD * 128 + NT * 164 + 128) * sizeof(float);
    cudaFuncSetAttribute(node_update_kernel,
                         cudaFuncAttributeMaxDynamicSharedMemorySize, (int)nu_smem);

    // --- CSR build ---
    zero_small_kernel<<<256, 256>>>();
    count_kernel<<<(NI + 255) / 256, 256>>>(inod, ihed);
    scan_blocks_kernel<<<NPART, 256>>>();
    scan_top_kernel<<<1, 512>>>();
    scan_add_kernel<<<NPART, 256>>>();
    fill_kernel<<<(NI + 255) / 256, 256>>>(inod, ihed);

    // --- layer-invariant node attr means + embed ---
    attr_gather_kernel<<<(NN * 16) / 256, 256>>>(attr);
    embed_kernel<<<592, 256>>>(x, W_embed, b_embed);

    // --- 3 message-passing layers ---
    for (int l = 0; l < NL; l++) {
        gather_n2h_kernel<<<(NH * 16) / 256, 256>>>();
        gather_h2n_kernel<<<(NN * 16) / 256, 256>>>();
        node_update_kernel<<<296, 256, nu_smem>>>(Wf, bf, Wc, bc, l);
    }

    // --- pooling + head ---
    pool_kernel<<<(NN * 16) / 256, 256>>>(batch);
    head_kernel<<<NG, HOUT>>>(W_proj, b_proj, W_out, b_out, out);
}